// round 2
// baseline (speedup 1.0000x reference)
#include <cuda_runtime.h>
#include <math.h>

namespace {
constexpr int B_ = 64, S_ = 512, I_ = 768, H_ = 512, G4 = 2048;
constexpr int BM = 128, BN = 64, BK = 32, NTILE = I_ / BK;
constexpr int HS_LD = 516;
constexpr int REC_SMEM = (64 * HS_LD + 512 * 32 + 64 * 32 + 512) * 4;
}

__device__ float g_xp[2][(size_t)S_ * B_ * G4];
__device__ float g_h[2][B_ * H_];
__device__ unsigned g_gen, g_count;

__global__ void init_sync_kernel() { g_gen = 0u; g_count = 0u; }

__device__ __forceinline__ unsigned f2tf(float x) {
    unsigned r; asm("cvt.rna.tf32.f32 %0, %1;" : "=r"(r) : "f"(x)); return r;
}
__device__ __forceinline__ void split_tf32(float v, unsigned& hi, unsigned& lo) {
    hi = f2tf(v); lo = f2tf(v - __uint_as_float(hi));
}
__device__ __forceinline__ void mma_tf32(float c[4], const unsigned a[4],
                                         unsigned b0, unsigned b1) {
    asm volatile(
        "mma.sync.aligned.m16n8k8.row.col.f32.tf32.tf32.f32 "
        "{%0,%1,%2,%3}, {%4,%5,%6,%7}, {%8,%9}, {%0,%1,%2,%3};"
        : "+f"(c[0]), "+f"(c[1]), "+f"(c[2]), "+f"(c[3])
        : "r"(a[0]), "r"(a[1]), "r"(a[2]), "r"(a[3]), "r"(b0), "r"(b1));
}

// C[(b,s), n] = x[(b,s), :] @ Wi[:, n] + bi[n] + bh[n]  -> g_xp[d][s][b][n]
extern "C" __global__ void __launch_bounds__(256, 2)
xproj_gemm(const float* __restrict__ x,
           const float* __restrict__ Wi_f, const float* __restrict__ bi_f,
           const float* __restrict__ bh_f,
           const float* __restrict__ Wi_b, const float* __restrict__ bi_b,
           const float* __restrict__ bh_b) {
    const int d = blockIdx.z;
    const float* __restrict__ Wp = d ? Wi_b : Wi_f;
    const float* __restrict__ b1p = d ? bi_b : bi_f;
    const float* __restrict__ b2p = d ? bh_b : bh_f;
    float* __restrict__ xp = g_xp[d];

    __shared__ float As[BM * 36];
    __shared__ float Bs[BK * 72];

    const int tid = threadIdx.x;
    const int wid = tid >> 5, lane = tid & 31;
    const int wm = wid >> 1, wn = wid & 1;
    const int gid = lane >> 2, tig = lane & 3;
    const int m0 = blockIdx.y * BM, n0 = blockIdx.x * BN;
    const int bb = m0 >> 9, s0 = m0 & 511;
    const float* Ag = x + ((size_t)bb * S_ + s0) * I_;

    const int ar = tid >> 3, ak = (tid & 7) * 4;
    const int br = tid >> 4, bn = (tid & 15) * 4;

    float acc[2][4][4];
#pragma unroll
    for (int mi = 0; mi < 2; ++mi)
#pragma unroll
        for (int ni = 0; ni < 4; ++ni)
#pragma unroll
            for (int j = 0; j < 4; ++j) acc[mi][ni][j] = 0.f;

    for (int t = 0; t < NTILE; ++t) {
        const int kt = t * BK;
        float4 pa[4], pb[2];
#pragma unroll
        for (int j = 0; j < 4; ++j)
            pa[j] = *(const float4*)(Ag + (size_t)(ar + 32 * j) * I_ + kt + ak);
#pragma unroll
        for (int j = 0; j < 2; ++j)
            pb[j] = *(const float4*)(Wp + (size_t)(kt + br + 16 * j) * G4 + n0 + bn);
        __syncthreads();
#pragma unroll
        for (int j = 0; j < 4; ++j) *(float4*)&As[(ar + 32 * j) * 36 + ak] = pa[j];
#pragma unroll
        for (int j = 0; j < 2; ++j) *(float4*)&Bs[(br + 16 * j) * 72 + bn] = pb[j];
        __syncthreads();

#pragma unroll
        for (int ks = 0; ks < 4; ++ks) {
            const int k0 = ks * 8;
            unsigned ah[2][4], al[2][4];
#pragma unroll
            for (int mi = 0; mi < 2; ++mi) {
                const float* ap = As + (wm * 32 + mi * 16) * 36 + k0;
                split_tf32(ap[gid * 36 + tig],        ah[mi][0], al[mi][0]);
                split_tf32(ap[(gid + 8) * 36 + tig],  ah[mi][1], al[mi][1]);
                split_tf32(ap[gid * 36 + tig + 4],    ah[mi][2], al[mi][2]);
                split_tf32(ap[(gid + 8) * 36 + tig+4],ah[mi][3], al[mi][3]);
            }
            unsigned bh2[4][2], bl2[4][2];
#pragma unroll
            for (int ni = 0; ni < 4; ++ni) {
                const float* bp = Bs + (k0 + tig) * 72 + wn * 32 + ni * 8 + gid;
                split_tf32(bp[0],      bh2[ni][0], bl2[ni][0]);
                split_tf32(bp[4 * 72], bh2[ni][1], bl2[ni][1]);
            }
#pragma unroll
            for (int mi = 0; mi < 2; ++mi)
#pragma unroll
                for (int ni = 0; ni < 4; ++ni) {
                    mma_tf32(acc[mi][ni], ah[mi], bh2[ni][0], bh2[ni][1]);
                    mma_tf32(acc[mi][ni], ah[mi], bl2[ni][0], bl2[ni][1]);
                    mma_tf32(acc[mi][ni], al[mi], bh2[ni][0], bh2[ni][1]);
                }
        }
    }

#pragma unroll
    for (int mi = 0; mi < 2; ++mi) {
        const int sA = s0 + wm * 32 + mi * 16 + gid;
#pragma unroll
        for (int ni = 0; ni < 4; ++ni) {
            const int gn = n0 + wn * 32 + ni * 8 + 2 * tig;
            const float c0 = b1p[gn] + b2p[gn];
            const float c1 = b1p[gn + 1] + b2p[gn + 1];
            *(float2*)&xp[((size_t)sA * B_ + bb) * G4 + gn] =
                make_float2(acc[mi][ni][0] + c0, acc[mi][ni][1] + c1);
            *(float2*)&xp[((size_t)(sA + 8) * B_ + bb) * G4 + gn] =
                make_float2(acc[mi][ni][2] + c0, acc[mi][ni][3] + c1);
        }
    }
}

__device__ __forceinline__ float sigmf(float x) { return 1.0f / (1.0f + expf(-x)); }

__device__ __forceinline__ void grid_bar(unsigned tgt, unsigned nblk) {
    __syncthreads();
    if (threadIdx.x == 0) {
        __threadfence();
        unsigned arr = atomicAdd(&g_count, 1u) + 1u;
        if (arr == nblk * tgt) atomicExch(&g_gen, tgt);
        else while (atomicAdd(&g_gen, 0u) < tgt) __nanosleep(64);
        __threadfence();
    }
    __syncthreads();
}

// 128 persistent blocks; dir = blk>>6; each block owns 8 hidden units (32 gate cols).
extern "C" __global__ void __launch_bounds__(256, 1)
lstm_recur(const float* __restrict__ sent, float* __restrict__ out,
           const float* __restrict__ Wh_f, const float* __restrict__ Wh_b) {
    const int blk = blockIdx.x, d = blk >> 6, u0 = (blk & 63) * 8;
    const float* __restrict__ Wh = d ? Wh_b : Wh_f;
    float* __restrict__ hg = g_h[d];
    const float* __restrict__ xp = g_xp[d];

    extern __shared__ float sm[];
    float* hs = sm;                      // [64][516]
    float* Ws = sm + 64 * HS_LD;         // [512][32]  col c -> gate (c>>3), unit u0+(c&7)
    float* gb = Ws + 512 * 32;           // [64][32]
    float* cs = gb + 64 * 32;            // [64][8]

    const int tid = threadIdx.x;
    for (int i = tid; i < 512 * 32; i += 256) {
        const int k = i >> 5, c = i & 31;
        Ws[i] = Wh[(size_t)k * G4 + (c >> 3) * H_ + u0 + (c & 7)];
    }
    for (int i = tid; i < 512; i += 256) {
        cs[i] = 0.f;
        hg[(i >> 3) * H_ + u0 + (i & 7)] = 0.f;
    }
    unsigned barno = 1;
    grid_bar(barno, gridDim.x);

    const int w = tid >> 5, l = tid & 31;
    const int cg = (l & 3) + ((w & 1) << 2);
    const int bg = (l >> 2) + ((w >> 1) << 3);
    const int b0r = bg * 2, b1r = b0r + 1, cc0 = cg * 4;
    const int gcol0 = (cc0 >> 3) * H_ + u0 + (cc0 & 7);

    for (int t = 0; t < S_; ++t) {
        const int tt = d ? (S_ - 1 - t) : t;

        for (int i = tid; i < 64 * 128; i += 256) {
            const int b = i >> 7, q = (i & 127) << 2;
            *(float4*)&hs[b * HS_LD + q] = *(const float4*)&hg[b * H_ + q];
        }
        __syncthreads();

        float a00=0.f,a01=0.f,a02=0.f,a03=0.f,a10=0.f,a11=0.f,a12=0.f,a13=0.f;
        const float* hp0 = hs + b0r * HS_LD;
        const float* hp1 = hs + b1r * HS_LD;
        const float* wp = Ws + cc0;
#pragma unroll 4
        for (int k = 0; k < H_; k += 4) {
            const float4 h0 = *(const float4*)(hp0 + k);
            const float4 h1 = *(const float4*)(hp1 + k);
            const float4 w0 = *(const float4*)(wp + (k + 0) * 32);
            const float4 w1 = *(const float4*)(wp + (k + 1) * 32);
            const float4 w2 = *(const float4*)(wp + (k + 2) * 32);
            const float4 w3 = *(const float4*)(wp + (k + 3) * 32);
#define SF(hc0, hc1, wv) \
            a00 += (hc0)*(wv).x; a01 += (hc0)*(wv).y; a02 += (hc0)*(wv).z; a03 += (hc0)*(wv).w; \
            a10 += (hc1)*(wv).x; a11 += (hc1)*(wv).y; a12 += (hc1)*(wv).z; a13 += (hc1)*(wv).w;
            SF(h0.x, h1.x, w0) SF(h0.y, h1.y, w1) SF(h0.z, h1.z, w2) SF(h0.w, h1.w, w3)
#undef SF
        }
        {
            const float4 x0 = *(const float4*)&xp[((size_t)tt * B_ + b0r) * G4 + gcol0];
            const float4 x1 = *(const float4*)&xp[((size_t)tt * B_ + b1r) * G4 + gcol0];
            gb[b0r*32+cc0+0]=a00+x0.x; gb[b0r*32+cc0+1]=a01+x0.y;
            gb[b0r*32+cc0+2]=a02+x0.z; gb[b0r*32+cc0+3]=a03+x0.w;
            gb[b1r*32+cc0+0]=a10+x1.x; gb[b1r*32+cc0+1]=a11+x1.y;
            gb[b1r*32+cc0+2]=a12+x1.z; gb[b1r*32+cc0+3]=a13+x1.w;
        }
        __syncthreads();

#pragma unroll
        for (int pp = 0; pp < 2; ++pp) {
            const int p = tid * 2 + pp, b = p >> 3, u = p & 7;
            const float xi = gb[b*32+u],      xf = gb[b*32+8+u];
            const float xg = gb[b*32+16+u],   xo = gb[b*32+24+u];
            const float st = sent[(size_t)b * S_ + tt];
            const float iv = sigmf(xi) * st;
            const float fv = sigmf(xf) * (1.0f + st);
            const float cv = fv * cs[b*8+u] + iv * tanhf(xg);
            cs[b*8+u] = cv;
            const float hv = sigmf(xo) * tanhf(cv);
            hg[b * H_ + u0 + u] = hv;
            out[((size_t)b * S_ + tt) * (2 * H_) + d * H_ + u0 + u] = hv;
        }
        ++barno;
        grid_bar(barno, gridDim.x);
    }
}

extern "C" void kernel_launch(void* const* d_in, const int* in_sizes, int n_in,
                              void* d_out, int out_size) {
    const float* x    = (const float*)d_in[0];
    const float* sent = (const float*)d_in[1];
    const float* Wi_f = (const float*)d_in[2];
    const float* bi_f = (const float*)d_in[3];
    const float* Wh_f = (const float*)d_in[4];
    const float* bh_f = (const float*)d_in[5];
    const float* Wi_b = (const float*)d_in[6];
    const float* bi_b = (const float*)d_in[7];
    const float* Wh_b = (const float*)d_in[8];
    // d_in[9] = bh_b
    const float* bh_b = (const float*)d_in[9];
    float* out = (float*)d_out;

    static bool attr_done = false;
    if (!attr_done) {
        cudaFuncSetAttribute(lstm_recur, cudaFuncAttributeMaxDynamicSharedMemorySize,
                             REC_SMEM);
        attr_done = true;
    }

    dim3 ggrid(G4 / BN, (B_ * S_) / BM, 2);
    xproj_gemm<<<ggrid, 256>>>(x, Wi_f, bi_f, bh_f, Wi_b, bi_b, bh_b);
    init_sync_kernel<<<1, 1>>>();
    lstm_recur<<<128, 256, REC_SMEM>>>(sent, out, Wh_f, Wh_b);
}

// round 5
// speedup vs baseline: 1.0789x; 1.0789x over previous
#include <cuda_runtime.h>
#include <math.h>

namespace {
constexpr int B_ = 64, S_ = 512, I_ = 768, H_ = 512, G4 = 2048;
constexpr int BM = 128, BN = 64, BK = 32, NTILE = I_ / BK;
constexpr int HS_LD = 516;
constexpr int REC_SMEM = (64 * HS_LD + 512 * 32 + 64 * 32 + 512) * 4;
constexpr int GEMM_SMEM = (2 * BM * 36 + 2 * BK * 72) * 4;  // hi/lo planes
}

__device__ float g_xp[2][(size_t)S_ * B_ * G4];
__device__ float g_h[2][2][B_ * H_];        // [dir][buf][b*H+h]
__device__ unsigned g_gen, g_count;

__global__ void init_sync_kernel() { g_gen = 0u; g_count = 0u; }

// ---------------- f32x2 helpers ----------------
__device__ __forceinline__ void ffma2(unsigned long long& acc,
                                      unsigned long long a, unsigned long long b) {
    asm("fma.rn.f32x2 %0, %1, %2, %0;" : "+l"(acc) : "l"(a), "l"(b));
}
__device__ __forceinline__ unsigned long long bcast2(float x) {
    unsigned long long r; unsigned u = __float_as_uint(x);
    asm("mov.b64 %0, {%1, %1};" : "=l"(r) : "r"(u));
    return r;
}
__device__ __forceinline__ float2 unpack2(unsigned long long v) {
    unsigned lo, hi;
    asm("mov.b64 {%0, %1}, %2;" : "=r"(lo), "=r"(hi) : "l"(v));
    return make_float2(__uint_as_float(lo), __uint_as_float(hi));
}

// ---------------- tf32 helpers ----------------
__device__ __forceinline__ unsigned f2tf(float x) {
    unsigned r; asm("cvt.rna.tf32.f32 %0, %1;" : "=r"(r) : "f"(x)); return r;
}
__device__ __forceinline__ void split4(const float4& v, uint4& hi, uint4& lo) {
    hi.x = f2tf(v.x); lo.x = f2tf(v.x - __uint_as_float(hi.x));
    hi.y = f2tf(v.y); lo.y = f2tf(v.y - __uint_as_float(hi.y));
    hi.z = f2tf(v.z); lo.z = f2tf(v.z - __uint_as_float(hi.z));
    hi.w = f2tf(v.w); lo.w = f2tf(v.w - __uint_as_float(hi.w));
}
__device__ __forceinline__ void mma_tf32(float c[4], const unsigned a[4],
                                         unsigned b0, unsigned b1) {
    asm volatile(
        "mma.sync.aligned.m16n8k8.row.col.f32.tf32.tf32.f32 "
        "{%0,%1,%2,%3}, {%4,%5,%6,%7}, {%8,%9}, {%0,%1,%2,%3};"
        : "+f"(c[0]), "+f"(c[1]), "+f"(c[2]), "+f"(c[3])
        : "r"(a[0]), "r"(a[1]), "r"(a[2]), "r"(a[3]), "r"(b0), "r"(b1));
}

// C[(b,s), n] = x[(b,s), :] @ Wi[:, n] + bi[n] + bh[n]  -> g_xp[d][s][b][n]
// tf32x3; hi/lo split done ONCE per element at tile load into smem planes.
extern "C" __global__ void __launch_bounds__(256, 2)
xproj_gemm(const float* __restrict__ x,
           const float* __restrict__ Wi_f, const float* __restrict__ bi_f,
           const float* __restrict__ bh_f,
           const float* __restrict__ Wi_b, const float* __restrict__ bi_b,
           const float* __restrict__ bh_b) {
    const int d = blockIdx.z;
    const float* __restrict__ Wp = d ? Wi_b : Wi_f;
    const float* __restrict__ b1p = d ? bi_b : bi_f;
    const float* __restrict__ b2p = d ? bh_b : bh_f;
    float* __restrict__ xp = g_xp[d];

    extern __shared__ unsigned smg[];
    unsigned* Ah = smg;                   // [128][36]
    unsigned* Al = Ah + BM * 36;
    unsigned* Bh = Al + BM * 36;          // [32][72]
    unsigned* Bl = Bh + BK * 72;

    const int tid = threadIdx.x;
    const int wid = tid >> 5, lane = tid & 31;
    const int wm = wid >> 1, wn = wid & 1;
    const int gid = lane >> 2, tig = lane & 3;
    const int m0 = blockIdx.y * BM, n0 = blockIdx.x * BN;
    const int bb = m0 >> 9, s0 = m0 & 511;
    const float* Ag = x + ((size_t)bb * S_ + s0) * I_;

    const int ar = tid >> 3, ak = (tid & 7) * 4;
    const int br = tid >> 4, bn = (tid & 15) * 4;

    float acc[2][4][4];
#pragma unroll
    for (int mi = 0; mi < 2; ++mi)
#pragma unroll
        for (int ni = 0; ni < 4; ++ni)
#pragma unroll
            for (int j = 0; j < 4; ++j) acc[mi][ni][j] = 0.f;

    for (int t = 0; t < NTILE; ++t) {
        const int kt = t * BK;
        float4 pa[4], pb[2];
#pragma unroll
        for (int j = 0; j < 4; ++j)
            pa[j] = *(const float4*)(Ag + (size_t)(ar + 32 * j) * I_ + kt + ak);
#pragma unroll
        for (int j = 0; j < 2; ++j)
            pb[j] = *(const float4*)(Wp + (size_t)(kt + br + 16 * j) * G4 + n0 + bn);
        __syncthreads();
#pragma unroll
        for (int j = 0; j < 4; ++j) {
            uint4 hi, lo; split4(pa[j], hi, lo);
            *(uint4*)&Ah[(ar + 32 * j) * 36 + ak] = hi;
            *(uint4*)&Al[(ar + 32 * j) * 36 + ak] = lo;
        }
#pragma unroll
        for (int j = 0; j < 2; ++j) {
            uint4 hi, lo; split4(pb[j], hi, lo);
            *(uint4*)&Bh[(br + 16 * j) * 72 + bn] = hi;
            *(uint4*)&Bl[(br + 16 * j) * 72 + bn] = lo;
        }
        __syncthreads();

#pragma unroll
        for (int ks = 0; ks < 4; ++ks) {
            const int k0 = ks * 8;
            unsigned ahr[2][4], alr[2][4];
#pragma unroll
            for (int mi = 0; mi < 2; ++mi) {
                const int base = wm * 32 + mi * 16;
                const int i0 = (base + gid) * 36 + k0 + tig;
                const int i1 = (base + gid + 8) * 36 + k0 + tig;
                ahr[mi][0] = Ah[i0];     alr[mi][0] = Al[i0];
                ahr[mi][1] = Ah[i1];     alr[mi][1] = Al[i1];
                ahr[mi][2] = Ah[i0 + 4]; alr[mi][2] = Al[i0 + 4];
                ahr[mi][3] = Ah[i1 + 4]; alr[mi][3] = Al[i1 + 4];
            }
            unsigned bhr[4][2], blr[4][2];
#pragma unroll
            for (int ni = 0; ni < 4; ++ni) {
                const int i0 = (k0 + tig) * 72 + wn * 32 + ni * 8 + gid;
                bhr[ni][0] = Bh[i0];          blr[ni][0] = Bl[i0];
                bhr[ni][1] = Bh[i0 + 4 * 72]; blr[ni][1] = Bl[i0 + 4 * 72];
            }
#pragma unroll
            for (int mi = 0; mi < 2; ++mi)
#pragma unroll
                for (int ni = 0; ni < 4; ++ni) {
                    mma_tf32(acc[mi][ni], ahr[mi], bhr[ni][0], bhr[ni][1]);
                    mma_tf32(acc[mi][ni], ahr[mi], blr[ni][0], blr[ni][1]);
                    mma_tf32(acc[mi][ni], alr[mi], bhr[ni][0], bhr[ni][1]);
                }
        }
    }

#pragma unroll
    for (int mi = 0; mi < 2; ++mi) {
        const int sA = s0 + wm * 32 + mi * 16 + gid;
#pragma unroll
        for (int ni = 0; ni < 4; ++ni) {
            const int gn = n0 + wn * 32 + ni * 8 + 2 * tig;
            const float c0 = b1p[gn] + b2p[gn];
            const float c1 = b1p[gn + 1] + b2p[gn + 1];
            *(float2*)&xp[((size_t)sA * B_ + bb) * G4 + gn] =
                make_float2(acc[mi][ni][0] + c0, acc[mi][ni][1] + c1);
            *(float2*)&xp[((size_t)(sA + 8) * B_ + bb) * G4 + gn] =
                make_float2(acc[mi][ni][2] + c0, acc[mi][ni][3] + c1);
        }
    }
}

__device__ __forceinline__ float sigmf(float x) { return 1.0f / (1.0f + expf(-x)); }

__device__ __forceinline__ void grid_bar(unsigned tgt, unsigned nblk) {
    __syncthreads();
    if (threadIdx.x == 0) {
        __threadfence();
        unsigned arr = atomicAdd(&g_count, 1u) + 1u;
        if (arr == nblk * tgt) atomicExch(&g_gen, tgt);
        else while (atomicAdd(&g_gen, 0u) < tgt) __nanosleep(64);
        __threadfence();
    }
    __syncthreads();
}

// 128 persistent blocks; dir = blk>>6; each block owns 8 hidden units (32 gate cols).
// f32x2 packed FMA: acc pairs across adjacent gate columns; h broadcast via mov.b64.
extern "C" __global__ void __launch_bounds__(256, 1)
lstm_recur(const float* __restrict__ sent, float* __restrict__ out,
           const float* __restrict__ Wh_f, const float* __restrict__ Wh_b) {
    const int blk = blockIdx.x, d = blk >> 6, u0 = (blk & 63) * 8;
    const float* __restrict__ Wh = d ? Wh_b : Wh_f;
    const float* __restrict__ xp = g_xp[d];

    extern __shared__ float sm[];
    float* hs = sm;                      // [64][516]
    float* Ws = sm + 64 * HS_LD;         // [512][32] col c -> gate (c>>3), unit u0+(c&7)
    float* gb = Ws + 512 * 32;           // [64][32]
    float* cs = gb + 64 * 32;            // [64][8]

    const int tid = threadIdx.x;
    for (int i = tid; i < 512 * 32; i += 256) {
        const int k = i >> 5, c = i & 31;
        Ws[i] = Wh[(size_t)k * G4 + (c >> 3) * H_ + u0 + (c & 7)];
    }
    for (int i = tid; i < 512; i += 256) {
        cs[i] = 0.f;
        g_h[d][0][(i >> 3) * H_ + u0 + (i & 7)] = 0.f;   // buf0 read at t=0
    }
    unsigned barno = 1;
    grid_bar(barno, gridDim.x);

    const int w = tid >> 5, l = tid & 31;
    const int cg = (l & 3) + ((w & 1) << 2);     // 8 col groups x 4 cols
    const int bg = (l >> 2) + ((w >> 1) << 3);   // 32 batch pairs
    const int b0r = bg * 2, b1r = b0r + 1, cc0 = cg * 4;
    const int gcol0 = (cc0 >> 3) * H_ + u0 + (cc0 & 7);

    for (int t = 0; t < S_; ++t) {
        const int tt = d ? (S_ - 1 - t) : t;
        const float* __restrict__ hr = g_h[d][t & 1];
        float* __restrict__ hw = g_h[d][1 - (t & 1)];

        for (int i = tid; i < 64 * 128; i += 256) {
            const int b = i >> 7, q = (i & 127) << 2;
            *(float4*)&hs[b * HS_LD + q] = *(const float4*)&hr[b * H_ + q];
        }
        // prefetch xp while staging completes
        const float4 x0 = *(const float4*)&xp[((size_t)tt * B_ + b0r) * G4 + gcol0];
        const float4 x1 = *(const float4*)&xp[((size_t)tt * B_ + b1r) * G4 + gcol0];
        __syncthreads();

        // acc[0]={r0,c01} acc[1]={r0,c23} acc[2]={r1,c01} acc[3]={r1,c23}
        unsigned long long acc0 = 0ull, acc1 = 0ull, acc2 = 0ull, acc3 = 0ull;
        const float* hp0 = hs + b0r * HS_LD;
        const float* hp1 = hs + b1r * HS_LD;
        const float* wp = Ws + cc0;
#pragma unroll 4
        for (int k = 0; k < H_; k += 4) {
            const float4 h0 = *(const float4*)(hp0 + k);
            const float4 h1 = *(const float4*)(hp1 + k);
            const ulonglong2 w0 = *(const ulonglong2*)(wp + (k + 0) * 32);
            const ulonglong2 w1 = *(const ulonglong2*)(wp + (k + 1) * 32);
            const ulonglong2 w2 = *(const ulonglong2*)(wp + (k + 2) * 32);
            const ulonglong2 w3 = *(const ulonglong2*)(wp + (k + 3) * 32);
#define KS(hc0, hc1, wv) { \
            const unsigned long long hh0 = bcast2(hc0), hh1 = bcast2(hc1); \
            ffma2(acc0, hh0, (wv).x); ffma2(acc1, hh0, (wv).y); \
            ffma2(acc2, hh1, (wv).x); ffma2(acc3, hh1, (wv).y); }
            KS(h0.x, h1.x, w0) KS(h0.y, h1.y, w1) KS(h0.z, h1.z, w2) KS(h0.w, h1.w, w3)
#undef KS
        }
        {
            const float2 a01 = unpack2(acc0), a23 = unpack2(acc1);
            const float2 b01 = unpack2(acc2), b23 = unpack2(acc3);
            gb[b0r*32+cc0+0] = a01.x + x0.x; gb[b0r*32+cc0+1] = a01.y + x0.y;
            gb[b0r*32+cc0+2] = a23.x + x0.z; gb[b0r*32+cc0+3] = a23.y + x0.w;
            gb[b1r*32+cc0+0] = b01.x + x1.x; gb[b1r*32+cc0+1] = b01.y + x1.y;
            gb[b1r*32+cc0+2] = b23.x + x1.z; gb[b1r*32+cc0+3] = b23.y + x1.w;
        }
        __syncthreads();

#pragma unroll
        for (int pp = 0; pp < 2; ++pp) {
            const int p = tid * 2 + pp, b = p >> 3, u = p & 7;
            const float xi = gb[b*32+u],    xf = gb[b*32+8+u];
            const float xg = gb[b*32+16+u], xo = gb[b*32+24+u];
            const float st = sent[(size_t)b * S_ + tt];
            const float iv = sigmf(xi) * st;
            const float fv = sigmf(xf) * (1.0f + st);
            const float cv = fv * cs[b*8+u] + iv * tanhf(xg);
            cs[b*8+u] = cv;
            const float hv = sigmf(xo) * tanhf(cv);
            hw[b * H_ + u0 + u] = hv;
            out[((size_t)b * S_ + tt) * (2 * H_) + d * H_ + u0 + u] = hv;
        }
        ++barno;
        grid_bar(barno, gridDim.x);
    }
}

extern "C" void kernel_launch(void* const* d_in, const int* in_sizes, int n_in,
                              void* d_out, int out_size) {
    const float* x    = (const float*)d_in[0];
    const float* sent = (const float*)d_in[1];
    const float* Wi_f = (const float*)d_in[2];
    const float* bi_f = (const float*)d_in[3];
    const float* Wh_f = (const float*)d_in[4];
    const float* bh_f = (const float*)d_in[5];
    const float* Wi_b = (const float*)d_in[6];
    const float* bi_b = (const float*)d_in[7];
    const float* Wh_b = (const float*)d_in[8];
    const float* bh_b = (const float*)d_in[9];
    float* out = (float*)d_out;

    static bool attr_done = false;
    if (!attr_done) {
        cudaFuncSetAttribute(lstm_recur, cudaFuncAttributeMaxDynamicSharedMemorySize,
                             REC_SMEM);
        cudaFuncSetAttribute(xproj_gemm, cudaFuncAttributeMaxDynamicSharedMemorySize,
                             GEMM_SMEM);
        attr_done = true;
    }

    dim3 ggrid(G4 / BN, (B_ * S_) / BM, 2);
    xproj_gemm<<<ggrid, 256, GEMM_SMEM>>>(x, Wi_f, bi_f, bh_f, Wi_b, bi_b, bh_b);
    init_sync_kernel<<<1, 1>>>();
    lstm_recur<<<128, 256, REC_SMEM>>>(sent, out, Wh_f, Wh_b);
}